// round 4
// baseline (speedup 1.0000x reference)
#include <cuda_runtime.h>
#include <cuda_fp16.h>
#include <cstdint>
#include <cstddef>

// Problem constants (fixed shapes)
#define Mtot   8192
#define Ltot   256
#define Qd     21
#define QQ     441
#define APAD   22              // a padded to 22 (11 half2 words)
#define JPB    464             // fp16 per (i,j) block: 21*22=462 -> pad 464 (928 B)
#define TILE_M 512
#define JC     16              // j's per chunk
#define NMT    (Mtot / TILE_M)         // 16
#define NBLK_MAIN (Ltot * NMT)         // 4096
#define NPAIR  (Ltot * Ltot)           // 65536
#define LAMBDA_H_F 1e-6f
#define LAMBDA_J_F 1e-4f
#define LOG2E_F 1.44269504088896f
#define LN2_F   0.69314718055995f

// Static device scratch
__device__ unsigned char g_X8[Mtot * Ltot];           // 2 MB
__device__ __half g_Jh[(size_t)NPAIR * JPB];          // 58 MB transposed fp16 J*log2e
__device__ float g_partial[NBLK_MAIN];
__device__ float g_regjT[NPAIR];

// ---------------------------------------------------------------------------
// Kernel 1: X int32 -> uint8
// ---------------------------------------------------------------------------
__global__ void k_x8(const int* __restrict__ X) {
    int t = blockIdx.x * blockDim.x + threadIdx.x;
    if (t < Mtot * Ltot) g_X8[t] = (unsigned char)X[t];
}

// ---------------------------------------------------------------------------
// Kernel 2: per-(i,j) transpose J[a][b] -> fp16 [b][a_pad] * LOG2E, + regJ.
// ---------------------------------------------------------------------------
__global__ void __launch_bounds__(128) k_prep(const float* __restrict__ J) {
    const int blk = blockIdx.x;
    const int i = blk >> 8, j = blk & 255;
    const int tid = threadIdx.x;
    __shared__ float s[QQ];
    __shared__ float red[4];

    if (j >= i) {
        if (tid == 0) g_regjT[blk] = 0.f;
        return;
    }

    float sq = 0.f;
    for (int t = tid; t < QQ; t += 128) {
        float v = J[(size_t)blk * QQ + t];
        s[t] = v;
        sq += v * v;
    }
    #pragma unroll
    for (int o = 16; o; o >>= 1) sq += __shfl_xor_sync(0xffffffffu, sq, o);
    if ((tid & 31) == 0) red[tid >> 5] = sq;
    __syncthreads();
    if (tid == 0) g_regjT[blk] = red[0] + red[1] + red[2] + red[3];

    __half* dst = g_Jh + (size_t)blk * JPB;
    for (int t = tid; t < JPB; t += 128) {
        int b = t / APAD;
        int a = t - b * APAD;
        float v = (t < Qd * APAD && a < Qd) ? s[a * Qd + b] * LOG2E_F : 0.f;
        dst[t] = __float2half(v);
    }
}

// ---------------------------------------------------------------------------
// Kernel 3: main gather. CTA = (position i, tile of 512 m).
// Inner: LDS.32 (half2) + HADD2, flush to f32x2 per 16-j chunk.
// Epilogue in log2-domain with ex2.approx.f16x2.
// ---------------------------------------------------------------------------
__device__ __forceinline__ void cp_async16(void* s, const void* g) {
    unsigned sa = (unsigned)__cvta_generic_to_shared(s);
    asm volatile("cp.async.cg.shared.global [%0], [%1], 16;" :: "r"(sa), "l"(g));
}

#define CHUNK_HALF (JC * JPB)            // 7424 half = 14848 B
#define CHUNK_F4   (CHUNK_HALF / 8)      // 928

__global__ void __launch_bounds__(TILE_M, 2) k_main(
    const float* __restrict__ W,
    const float* __restrict__ h)
{
    __shared__ __align__(16) __half sJ[2][CHUNK_HALF];
    __shared__ float sH[APAD];
    __shared__ float sRed[TILE_M / 32];

    const int bid = blockIdx.x;
    const int i   = (Ltot - 1) - (bid >> 4);   // descending i: big work first
    const int mt  = bid & (NMT - 1);
    const int tid = threadIdx.x;
    const int m   = mt * TILE_M + tid;

    // y = logit * log2e; pad slot -> -30 (exp2 -> 0)
    if (tid < APAD) sH[tid] = (tid < Qd) ? h[i * Qd + tid] * LOG2E_F : -30.0f;

    const __half* Jrow = g_Jh + (size_t)i * (Ltot * JPB);
    const int full = i >> 4;
    const int rem  = i & 15;
    const int nc   = full + (rem ? 1 : 0);

    if (nc > 0) {
        const float4* src = (const float4*)Jrow;
        float4* dst = (float4*)sJ[0];
        #pragma unroll
        for (int k = 0; k < 2; ++k) {
            int idx = tid + k * TILE_M;
            if (idx < CHUNK_F4) cp_async16(dst + idx, src + idx);
        }
    }
    asm volatile("cp.async.commit_group;");
    __syncthreads();

    // fp32 accumulators as 11 packed f32x2
    uint64_t acc2[11];
    #pragma unroll
    for (int k = 0; k < 11; ++k) {
        uint32_t lo = __float_as_uint(sH[2 * k]);
        uint32_t hi = __float_as_uint(sH[2 * k + 1]);
        asm("mov.b64 %0, {%1, %2};" : "=l"(acc2[k]) : "r"(lo), "r"(hi));
    }

    const unsigned char* xrow = g_X8 + (size_t)m * Ltot;

    for (int c = 0; c < nc; ++c) {
        const int buf = c & 1;
        if (c + 1 < nc) {
            const float4* src = (const float4*)(Jrow + (size_t)(c + 1) * CHUNK_HALF);
            float4* dst = (float4*)sJ[buf ^ 1];
            #pragma unroll
            for (int k = 0; k < 2; ++k) {
                int idx = tid + k * TILE_M;
                if (idx < CHUNK_F4) cp_async16(dst + idx, src + idx);
            }
        }
        asm volatile("cp.async.commit_group;");

        const uint4 xv = *(const uint4*)(xrow + c * JC);

        if (c + 1 < nc) { asm volatile("cp.async.wait_group 1;"); }
        else            { asm volatile("cp.async.wait_group 0;"); }
        __syncthreads();

        const __half2* base = (const __half2*)sJ[buf];
        const int cnt = (c == full) ? rem : JC;

        __half2 hacc[11];
        #pragma unroll
        for (int k = 0; k < 11; ++k) hacc[k] = __half2half2(__ushort_as_half(0));

        const uint32_t xw[4] = {xv.x, xv.y, xv.z, xv.w};
        if (cnt == JC) {
            #pragma unroll
            for (int w = 0; w < 4; ++w) {
                #pragma unroll
                for (int s = 0; s < 4; ++s) {
                    const int jj = w * 4 + s;
                    const int b = (int)((xw[w] >> (8 * s)) & 0xffu);
                    const __half2* p = base + jj * (JPB / 2) + b * (APAD / 2);
                    #pragma unroll
                    for (int k = 0; k < 11; ++k) hacc[k] = __hadd2(hacc[k], p[k]);
                }
            }
        } else {
            for (int jj = 0; jj < cnt; ++jj) {
                const int b = (int)((xw[jj >> 2] >> (8 * (jj & 3))) & 0xffu);
                const __half2* p = base + jj * (JPB / 2) + b * (APAD / 2);
                #pragma unroll
                for (int k = 0; k < 11; ++k) hacc[k] = __hadd2(hacc[k], p[k]);
            }
        }

        // Flush chunk partials into fp32 accumulators
        #pragma unroll
        for (int k = 0; k < 11; ++k) {
            float2 f = __half22float2(hacc[k]);
            uint64_t v;
            asm("mov.b64 %0, {%1, %2};" : "=l"(v)
                : "r"(__float_as_uint(f.x)), "r"(__float_as_uint(f.y)));
            asm("add.rn.f32x2 %0, %0, %1;" : "+l"(acc2[k]) : "l"(v));
        }
        __syncthreads();
    }

    // Unpack accumulators: y[a] = logit[a] * log2e
    float acc[APAD];
    #pragma unroll
    for (int k = 0; k < 11; ++k) {
        uint32_t lo, hi;
        asm("mov.b64 {%0, %1}, %2;" : "=r"(lo), "=r"(hi) : "l"(acc2[k]));
        acc[2 * k]     = __uint_as_float(lo);
        acc[2 * k + 1] = __uint_as_float(hi);
    }

    // Epilogue: loss_token = ln2 * (log2(sum_a 2^y[a]) - y[gold]), weighted
    const int bi  = (int)xrow[i];
    const float w = W[m];
    float ygold = 0.f;
    #pragma unroll
    for (int a = 0; a < Qd; ++a) if (a == bi) ygold = acc[a];

    float S = 0.f;
    #pragma unroll
    for (int k = 0; k < 11; ++k) {
        uint32_t yh, eh;
        asm("cvt.rn.f16x2.f32 %0, %1, %2;" : "=r"(yh)
            : "f"(acc[2 * k + 1]), "f"(acc[2 * k]));
        asm("ex2.approx.f16x2 %0, %1;" : "=r"(eh) : "r"(yh));
        __half2 h2 = *reinterpret_cast<__half2*>(&eh);
        float2 f = __half22float2(h2);
        S += f.x + f.y;                 // pad slot contributes 2^-30 -> 0
    }
    float v = w * (LN2_F * (__log2f(S) - ygold));

    #pragma unroll
    for (int o = 16; o; o >>= 1) v += __shfl_xor_sync(0xffffffffu, v, o);
    if ((tid & 31) == 0) sRed[tid >> 5] = v;
    __syncthreads();
    if (tid == 0) {
        float t = 0.f;
        #pragma unroll
        for (int k = 0; k < TILE_M / 32; ++k) t += sRed[k];
        g_partial[bid] = t;
    }
}

// ---------------------------------------------------------------------------
// Kernel 4: final deterministic reduction + regularizers
// ---------------------------------------------------------------------------
__global__ void k_final(const float* __restrict__ h, float* __restrict__ out) {
    const int tid = threadIdx.x;
    float v = 0.f;
    for (int t = tid; t < NBLK_MAIN; t += 1024) v += g_partial[t];
    float rj = 0.f;
    for (int t = tid; t < NPAIR; t += 1024) rj += g_regjT[t];
    float rh = 0.f;
    for (int t = tid; t < Ltot * Qd; t += 1024) { float x = h[t]; rh += x * x; }
    float r = v + LAMBDA_J_F * rj + LAMBDA_H_F * rh;
    #pragma unroll
    for (int o = 16; o; o >>= 1) r += __shfl_xor_sync(0xffffffffu, r, o);
    __shared__ float red[32];
    if ((tid & 31) == 0) red[tid >> 5] = r;
    __syncthreads();
    if (tid == 0) {
        float t = 0.f;
        #pragma unroll
        for (int k = 0; k < 32; ++k) t += red[k];
        out[0] = t;
    }
}

// ---------------------------------------------------------------------------
// Launch
// ---------------------------------------------------------------------------
extern "C" void kernel_launch(void* const* d_in, const int* in_sizes, int n_in,
                              void* d_out, int out_size) {
    const int*   X = (const int*)d_in[0];      // (M, L) int32
    const float* W = (const float*)d_in[1];    // (M,)
    const float* h = (const float*)d_in[2];    // (L, Q)
    const float* J = (const float*)d_in[3];    // (L, L, Q, Q)
    float* out = (float*)d_out;

    k_x8   <<<(Mtot * Ltot + 255) / 256, 256>>>(X);
    k_prep <<<NPAIR, 128>>>(J);
    k_main <<<NBLK_MAIN, TILE_M>>>(W, h);
    k_final<<<1, 1024>>>(h, out);
}

// round 6
// speedup vs baseline: 1.0787x; 1.0787x over previous
#include <cuda_runtime.h>
#include <cuda_fp16.h>
#include <cuda_fp8.h>
#include <cstdint>
#include <cstddef>

// Problem constants (fixed shapes)
#define Mtot   8192
#define Ltot   256
#define Qd     21
#define QQ     441
#define AP8    28              // fp8 a-stride in bytes (7 words, coprime with 32 banks)
#define JPB8   592             // block bytes: 21*28=588 -> pad 592 (16B multiple)
#define TILE_M 512
#define JC     16              // j's per chunk
#define NMT    (Mtot / TILE_M)         // 16
#define NBLK_MAIN (Ltot * NMT)         // 4096
#define NPAIR  (Ltot * Ltot)           // 65536
#define LAMBDA_H_F 1e-6f
#define LAMBDA_J_F 1e-4f
#define JSCALE    256.0f
#define INV_JSCALE (1.0f / 256.0f)

// Static device scratch
__device__ unsigned char g_X8[Mtot * Ltot];              // 2 MB
__device__ unsigned char g_J8[(size_t)NPAIR * JPB8];     // 38.8 MB fp8 (e4m3) J*256, [b][a]
__device__ float g_partial[NBLK_MAIN];
__device__ float g_regjT[NPAIR];

// ---------------------------------------------------------------------------
// Kernel 1: X int32 -> uint8
// ---------------------------------------------------------------------------
__global__ void k_x8(const int* __restrict__ X) {
    int t = blockIdx.x * blockDim.x + threadIdx.x;
    if (t < Mtot * Ltot) g_X8[t] = (unsigned char)X[t];
}

// ---------------------------------------------------------------------------
// Kernel 2: per-(i,j) transpose J[a][b] -> e4m3 [b][a]*256, + regJ partials.
// ---------------------------------------------------------------------------
__global__ void __launch_bounds__(128) k_prep(const float* __restrict__ J) {
    const int blk = blockIdx.x;
    const int i = blk >> 8, j = blk & 255;
    const int tid = threadIdx.x;
    __shared__ float s[QQ];
    __shared__ float red[4];

    if (j >= i) {
        if (tid == 0) g_regjT[blk] = 0.f;
        return;
    }

    float sq = 0.f;
    for (int t = tid; t < QQ; t += 128) {
        float v = J[(size_t)blk * QQ + t];
        s[t] = v;
        sq += v * v;
    }
    #pragma unroll
    for (int o = 16; o; o >>= 1) sq += __shfl_xor_sync(0xffffffffu, sq, o);
    if ((tid & 31) == 0) red[tid >> 5] = sq;
    __syncthreads();
    if (tid == 0) g_regjT[blk] = red[0] + red[1] + red[2] + red[3];

    unsigned char* dst = g_J8 + (size_t)blk * JPB8;
    for (int t = tid; t < JPB8; t += 128) {
        int b = t / AP8;
        int a = t - b * AP8;
        float v = (b < Qd && a < Qd) ? s[a * Qd + b] * JSCALE : 0.f;
        __nv_fp8_e4m3 f8(v);
        dst[t] = *reinterpret_cast<unsigned char*>(&f8);
    }
}

// ---------------------------------------------------------------------------
// Kernel 3: main gather. CTA = (position i, tile of 512 m).
// Inner per (thread, j): 6 LDS.32 (4x e4m3 each) -> cvt f16x2 -> HADD2.
// Flush fp16 chunk partials to packed f32x2 every 16 j. fp32 epilogue.
// ---------------------------------------------------------------------------
__device__ __forceinline__ void cp_async16(void* s, const void* g) {
    unsigned sa = (unsigned)__cvta_generic_to_shared(s);
    asm volatile("cp.async.cg.shared.global [%0], [%1], 16;" :: "r"(sa), "l"(g));
}

__device__ __forceinline__ uint32_t cvt_e4m3x2_f16x2(uint32_t pair16) {
    uint32_t r;
    asm("{\n\t"
        ".reg .b16 lo;\n\t"
        "cvt.u16.u32 lo, %1;\n\t"
        "cvt.rn.f16x2.e4m3x2 %0, lo;\n\t"
        "}" : "=r"(r) : "r"(pair16));
    return r;
}

__device__ __forceinline__ void gather_j(
    const unsigned char* base, int jj, int b, __half2* hacc)
{
    const uint32_t* p = (const uint32_t*)(base + jj * JPB8 + b * AP8);
    uint32_t u0 = p[0], u1 = p[1], u2 = p[2], u3 = p[3], u4 = p[4], u5 = p[5];

    uint32_t f;
    f = cvt_e4m3x2_f16x2(u0);       hacc[0] = __hadd2(hacc[0], *(__half2*)&f);
    f = cvt_e4m3x2_f16x2(u0 >> 16); hacc[1] = __hadd2(hacc[1], *(__half2*)&f);
    f = cvt_e4m3x2_f16x2(u1);       hacc[2] = __hadd2(hacc[2], *(__half2*)&f);
    f = cvt_e4m3x2_f16x2(u1 >> 16); hacc[3] = __hadd2(hacc[3], *(__half2*)&f);
    f = cvt_e4m3x2_f16x2(u2);       hacc[4] = __hadd2(hacc[4], *(__half2*)&f);
    f = cvt_e4m3x2_f16x2(u2 >> 16); hacc[5] = __hadd2(hacc[5], *(__half2*)&f);
    f = cvt_e4m3x2_f16x2(u3);       hacc[6] = __hadd2(hacc[6], *(__half2*)&f);
    f = cvt_e4m3x2_f16x2(u3 >> 16); hacc[7] = __hadd2(hacc[7], *(__half2*)&f);
    f = cvt_e4m3x2_f16x2(u4);       hacc[8] = __hadd2(hacc[8], *(__half2*)&f);
    f = cvt_e4m3x2_f16x2(u4 >> 16); hacc[9] = __hadd2(hacc[9], *(__half2*)&f);
    f = cvt_e4m3x2_f16x2(u5);       hacc[10] = __hadd2(hacc[10], *(__half2*)&f);
    // u5 high half covers lanes 22,23 = pad (not accumulated)
}

#define CHUNK_B   (JC * JPB8)            // 9472 bytes
#define CHUNK_F4  (CHUNK_B / 16)         // 592

__global__ void __launch_bounds__(TILE_M, 2) k_main(
    const float* __restrict__ W,
    const float* __restrict__ h)
{
    __shared__ __align__(16) unsigned char sJ[2][CHUNK_B];
    __shared__ float sH[Qd];
    __shared__ float sRed[TILE_M / 32];

    const int bid = blockIdx.x;
    const int i   = (Ltot - 1) - (bid >> 4);   // descending i: big work first
    const int mt  = bid & (NMT - 1);
    const int tid = threadIdx.x;
    const int m   = mt * TILE_M + tid;

    if (tid < Qd) sH[tid] = h[i * Qd + tid] * JSCALE;   // scaled domain

    const unsigned char* Jrow = g_J8 + (size_t)i * (Ltot * JPB8);
    const int full = i >> 4;
    const int rem  = i & 15;
    const int nc   = full + (rem ? 1 : 0);

    if (nc > 0) {
        const float4* src = (const float4*)Jrow;
        float4* dst = (float4*)sJ[0];
        #pragma unroll
        for (int k = 0; k < 2; ++k) {
            int idx = tid + k * TILE_M;
            if (idx < CHUNK_F4) cp_async16(dst + idx, src + idx);
        }
    }
    asm volatile("cp.async.commit_group;");
    __syncthreads();

    // fp32 accumulators as 11 packed f32x2 (scaled by 256); lane 21 is pad
    uint64_t acc2[11];
    #pragma unroll
    for (int k = 0; k < 11; ++k) {
        uint32_t lo = __float_as_uint(sH[2 * k]);
        uint32_t hi = (2 * k + 1 < Qd) ? __float_as_uint(sH[2 * k + 1]) : 0u;
        asm("mov.b64 %0, {%1, %2};" : "=l"(acc2[k]) : "r"(lo), "r"(hi));
    }

    const unsigned char* xrow = g_X8 + (size_t)m * Ltot;

    for (int c = 0; c < nc; ++c) {
        const int buf = c & 1;
        if (c + 1 < nc) {
            const float4* src = (const float4*)(Jrow + (size_t)(c + 1) * CHUNK_B);
            float4* dst = (float4*)sJ[buf ^ 1];
            #pragma unroll
            for (int k = 0; k < 2; ++k) {
                int idx = tid + k * TILE_M;
                if (idx < CHUNK_F4) cp_async16(dst + idx, src + idx);
            }
        }
        asm volatile("cp.async.commit_group;");

        const uint4 xv = *(const uint4*)(xrow + c * JC);

        if (c + 1 < nc) { asm volatile("cp.async.wait_group 1;"); }
        else            { asm volatile("cp.async.wait_group 0;"); }
        __syncthreads();

        const unsigned char* base = sJ[buf];
        const int cnt = (c == full) ? rem : JC;

        // fp16x2 chunk accumulators (lanes 0..21; lane 21 pad=0)
        __half2 hacc[11];
        #pragma unroll
        for (int k = 0; k < 11; ++k) hacc[k] = __half2half2(__ushort_as_half(0));

        const uint32_t xw[4] = {xv.x, xv.y, xv.z, xv.w};

        if (cnt == JC) {
            #pragma unroll
            for (int jj = 0; jj < JC; ++jj) {
                const int b = (int)((xw[jj >> 2] >> (8 * (jj & 3))) & 0xffu);
                gather_j(base, jj, b, hacc);
            }
        } else {
            for (int jj = 0; jj < cnt; ++jj) {
                const int b = (int)((xw[jj >> 2] >> (8 * (jj & 3))) & 0xffu);
                gather_j(base, jj, b, hacc);
            }
        }

        // Flush chunk partials into fp32 accumulators (still scaled)
        #pragma unroll
        for (int k = 0; k < 11; ++k) {
            float2 f = __half22float2(hacc[k]);
            uint64_t v;
            asm("mov.b64 %0, {%1, %2};" : "=l"(v)
                : "r"(__float_as_uint(f.x)), "r"(__float_as_uint(f.y)));
            asm("add.rn.f32x2 %0, %0, %1;" : "+l"(acc2[k]) : "l"(v));
        }
        __syncthreads();
    }

    // Unpack accumulators (scaled logits: z*256)
    float acc[Qd + 1];
    #pragma unroll
    for (int k = 0; k < 11; ++k) {
        uint32_t lo, hi;
        asm("mov.b64 {%0, %1}, %2;" : "=r"(lo), "=r"(hi) : "l"(acc2[k]));
        acc[2 * k]     = __uint_as_float(lo);
        acc[2 * k + 1] = __uint_as_float(hi);
    }

    // Epilogue (fp32): w * (log(sum exp(z)) - z_gold), z = acc/256
    const int bi  = (int)xrow[i];
    const float w = W[m];
    float mx = acc[0];
    #pragma unroll
    for (int a = 1; a < Qd; ++a) mx = fmaxf(mx, acc[a]);
    float S = 0.f, gold = 0.f;
    #pragma unroll
    for (int a = 0; a < Qd; ++a) {
        float e = (acc[a] - mx) * INV_JSCALE;
        S += __expf(e);
        if (a == bi) gold = e;
    }
    float v = w * (__logf(S) - gold);

    #pragma unroll
    for (int o = 16; o; o >>= 1) v += __shfl_xor_sync(0xffffffffu, v, o);
    if ((tid & 31) == 0) sRed[tid >> 5] = v;
    __syncthreads();
    if (tid == 0) {
        float t = 0.f;
        #pragma unroll
        for (int k = 0; k < TILE_M / 32; ++k) t += sRed[k];
        g_partial[bid] = t;
    }
}

// ---------------------------------------------------------------------------
// Kernel 4: final deterministic reduction + regularizers
// ---------------------------------------------------------------------------
__global__ void k_final(const float* __restrict__ h, float* __restrict__ out) {
    const int tid = threadIdx.x;
    float v = 0.f;
    for (int t = tid; t < NBLK_MAIN; t += 1024) v += g_partial[t];
    float rj = 0.f;
    for (int t = tid; t < NPAIR; t += 1024) rj += g_regjT[t];
    float rh = 0.f;
    for (int t = tid; t < Ltot * Qd; t += 1024) { float x = h[t]; rh += x * x; }
    float r = v + LAMBDA_J_F * rj + LAMBDA_H_F * rh;
    #pragma unroll
    for (int o = 16; o; o >>= 1) r += __shfl_xor_sync(0xffffffffu, r, o);
    __shared__ float red[32];
    if ((tid & 31) == 0) red[tid >> 5] = r;
    __syncthreads();
    if (tid == 0) {
        float t = 0.f;
        #pragma unroll
        for (int k = 0; k < 32; ++k) t += red[k];
        out[0] = t;
    }
}

// ---------------------------------------------------------------------------
// Launch
// ---------------------------------------------------------------------------
extern "C" void kernel_launch(void* const* d_in, const int* in_sizes, int n_in,
                              void* d_out, int out_size) {
    const int*   X = (const int*)d_in[0];      // (M, L) int32
    const float* W = (const float*)d_in[1];    // (M,)
    const float* h = (const float*)d_in[2];    // (L, Q)
    const float* J = (const float*)d_in[3];    // (L, L, Q, Q)
    float* out = (float*)d_out;

    k_x8   <<<(Mtot * Ltot + 255) / 256, 256>>>(X);
    k_prep <<<NPAIR, 128>>>(J);
    k_main <<<NBLK_MAIN, TILE_M>>>(W, h);
    k_final<<<1, 1024>>>(h, out);
}